// round 11
// baseline (speedup 1.0000x reference)
#include <cuda_runtime.h>
#include <math.h>
#include <stdint.h>

// ---------------- problem constants ----------------
namespace {
constexpr int Bn    = 16;
constexpr int E     = 768;
constexpr int HEADS = 12;
constexpr int Ll    = 12;
constexpr int MLPD  = 3072;
constexpr int OUTD  = 2048;
constexpr int PW    = 42;
constexpr int NPAT  = 168;
constexpr int SEQ   = 169;
constexpr int Nrow  = 2704;
constexpr int DH    = 64;
constexpr int E3    = 2304;
constexpr int E2    = 1536;
}

// ---------------- scratch (static device globals) ----------------
__device__ __align__(16) float    g_X   [Nrow * E];
__device__ __align__(16) uint32_t g_XN  [Nrow * E];
__device__ __align__(16) float    g_QKV [Nrow * E3];
__device__ __align__(16) uint32_t g_O   [Nrow * E];
__device__ __align__(16) uint32_t g_H1  [Nrow * MLPD];
__device__ __align__(16) uint32_t g_PT  [Bn * NPAT * E];
__device__ __align__(16) float    g_PE  [Bn * NPAT * E];
__device__ __align__(16) float    g_OUTP[Nrow * OUTD];

// pre-converted tf32 weights
__device__ __align__(16) uint32_t g_Wpatch[768 * 768];
__device__ __align__(16) uint32_t g_Win   [12 * 2304 * 768];
__device__ __align__(16) uint32_t g_Wout  [12 * 768 * 768];
__device__ __align__(16) uint32_t g_Wm1   [12 * 3072 * 768];
__device__ __align__(16) uint32_t g_Wm2   [12 * 768 * 3072];
__device__ __align__(16) uint32_t g_Wb1   [1536 * 768];
__device__ __align__(16) uint32_t g_Wb2   [2048 * 1536];

// ---------------- tf32 helpers ----------------
__device__ __forceinline__ uint32_t f2tf(float f)
{
    uint32_t r;
    asm("cvt.rna.tf32.f32 %0, %1;" : "=r"(r) : "f"(f));
    return r;
}

__device__ __forceinline__ void mma_tf32(float* c, const uint32_t* a, const uint32_t* b)
{
    asm volatile(
        "mma.sync.aligned.m16n8k8.row.col.f32.tf32.tf32.f32 "
        "{%0,%1,%2,%3}, {%4,%5,%6,%7}, {%8,%9}, {%0,%1,%2,%3};\n"
        : "+f"(c[0]), "+f"(c[1]), "+f"(c[2]), "+f"(c[3])
        : "r"(a[0]), "r"(a[1]), "r"(a[2]), "r"(a[3]), "r"(b[0]), "r"(b[1]));
}

// ---------------- weight conversion ----------------
__global__ void cvt_kernel(const float* __restrict__ src, uint32_t* __restrict__ dst, int n4)
{
    int i = blockIdx.x * blockDim.x + threadIdx.x;
    if (i >= n4) return;
    float4 v = ((const float4*)src)[i];
    uint4 o = make_uint4(f2tf(v.x), f2tf(v.y), f2tf(v.z), f2tf(v.w));
    ((uint4*)dst)[i] = o;
}

// ---------------- patchify (writes tf32) ----------------
__global__ void patchify_kernel(const float* __restrict__ px, uint32_t* __restrict__ PT)
{
    int idx = blockIdx.x * blockDim.x + threadIdx.x;
    if (idx >= Bn * NPAT * E) return;
    int k = idx % E;
    int m = idx / E;
    int b = m / NPAT, p = m % NPAT;
    int ph = p / PW, pw = p % PW;
    int c  = k >> 8;
    int r  = k & 255;
    int ii = r >> 4, jj = r & 15;
    PT[idx] = f2tf(px[(((size_t)(b * 3 + c) * 64 + ph * 16 + ii) * 672) + pw * 16 + jj]);
}

// ---------------- assemble ----------------
__global__ void assemble_kernel(const float* __restrict__ PE_, const float* __restrict__ cls,
                                const float* __restrict__ row_emb, const float* __restrict__ col_emb,
                                float* __restrict__ X)
{
    int idx = blockIdx.x * blockDim.x + threadIdx.x;
    if (idx >= Nrow * E) return;
    int e = idx % E;
    int n = idx / E;
    int b = n / SEQ, s = n % SEQ;
    float v;
    if (s == 0) {
        v = cls[e];
    } else {
        int p = s - 1, ph = p / PW, pw = p % PW;
        float pos = (e < 384) ? row_emb[ph * 384 + e] : col_emb[pw * 384 + (e - 384)];
        v = PE_[((size_t)(b * NPAT) + p) * E + e] + pos;
    }
    X[idx] = v;
}

// ---------------- LayerNorm (float4-vectorized; optional tf32 output) -------
__global__ void ln_kernel(const float* __restrict__ x, const float* __restrict__ g,
                          const float* __restrict__ b, void* __restrict__ y, int D, int cvtout)
{
    int row = blockIdx.x;
    const float4* xr = (const float4*)(x + (size_t)row * D);
    const int D4 = D >> 2;
    float s = 0.f, s2 = 0.f;
    for (int i = threadIdx.x; i < D4; i += blockDim.x) {
        float4 v = xr[i];
        s  += v.x + v.y + v.z + v.w;
        s2 += v.x * v.x + v.y * v.y + v.z * v.z + v.w * v.w;
    }
    __shared__ float shs[8], shs2[8];
    #pragma unroll
    for (int o = 16; o; o >>= 1) {
        s  += __shfl_xor_sync(~0u, s,  o);
        s2 += __shfl_xor_sync(~0u, s2, o);
    }
    int w = threadIdx.x >> 5, lane = threadIdx.x & 31;
    if (lane == 0) { shs[w] = s; shs2[w] = s2; }
    __syncthreads();
    if (w == 0) {
        s  = lane < 8 ? shs[lane]  : 0.f;
        s2 = lane < 8 ? shs2[lane] : 0.f;
        #pragma unroll
        for (int o = 4; o; o >>= 1) {
            s  += __shfl_xor_sync(~0u, s,  o);
            s2 += __shfl_xor_sync(~0u, s2, o);
        }
        if (lane == 0) { shs[0] = s; shs2[0] = s2; }
    }
    __syncthreads();
    float m   = shs[0] / (float)D;
    float var = shs2[0] / (float)D - m * m;
    float inv = rsqrtf(var + 1e-5f);
    const float4* gp = (const float4*)g;
    const float4* bp = (const float4*)b;
    if (cvtout) {
        uint4* yr = (uint4*)((uint32_t*)y + (size_t)row * D);
        for (int i = threadIdx.x; i < D4; i += blockDim.x) {
            float4 v = xr[i], gg = gp[i], bb = bp[i];
            uint4 o;
            o.x = f2tf((v.x - m) * inv * gg.x + bb.x);
            o.y = f2tf((v.y - m) * inv * gg.y + bb.y);
            o.z = f2tf((v.z - m) * inv * gg.z + bb.z);
            o.w = f2tf((v.w - m) * inv * gg.w + bb.w);
            yr[i] = o;
        }
    } else {
        float4* yr = (float4*)((float*)y + (size_t)row * D);
        for (int i = threadIdx.x; i < D4; i += blockDim.x) {
            float4 v = xr[i], gg = gp[i], bb = bp[i];
            float4 o;
            o.x = (v.x - m) * inv * gg.x + bb.x;
            o.y = (v.y - m) * inv * gg.y + bb.y;
            o.z = (v.z - m) * inv * gg.z + bb.z;
            o.w = (v.w - m) * inv * gg.w + bb.w;
            yr[i] = o;
        }
    }
}

// ---------------- GEMM epilogue helper ----------------
__device__ __forceinline__ void epi_store(void* Cout, size_t off, int c,
                                          float v0, float v1,
                                          const float* bias, const float* Res,
                                          int epi, int cvtout)
{
    v0 += bias[c];
    v1 += bias[c + 1];
    if (epi == 1) {
        v0 = 0.5f * v0 * (1.0f + erff(v0 * 0.70710678118654752f));
        v1 = 0.5f * v1 * (1.0f + erff(v1 * 0.70710678118654752f));
    } else if (epi == 2) {
        v0 += Res[off + c];
        v1 += Res[off + c + 1];
    }
    if (cvtout) {
        *(uint2*)((uint32_t*)Cout + off + c) = make_uint2(f2tf(v0), f2tf(v1));
    } else {
        *(float2*)((float*)Cout + off + c) = make_float2(v0, v1);
    }
}

// ---------------- TF32 tensor-core GEMM, 128x128 tile (round-8 structure) ---
// 256 threads = 8 warps of 32x64, BK=16 double-buffered, register prefetch,
// paired LDS.64 smem layout (PB=12), ONE barrier per slab.
// ROUND-11 CHANGE: __launch_bounds__(256, 2) -> cap 128 regs/thread so two
// blocks co-reside per SM (16 warps) and hide each other's barriers/latency.
constexpr int PB = 12;   // row stride in uint2 (8 used + 4 pad)

__global__ __launch_bounds__(256, 2) void gemm_tc(const uint32_t* __restrict__ A,
                                                  const uint32_t* __restrict__ W,
                                                  const float* __restrict__ bias,
                                                  const float* __restrict__ Res,
                                                  void* __restrict__ Cout,
                                                  int M, int K, int Nout, int epi, int cvtout)
{
    __shared__ __align__(16) uint2 As[2][128 * PB];
    __shared__ __align__(16) uint2 Bs[2][128 * PB];

    const int t = threadIdx.x;
    const int warp = t >> 5, lane = t & 31;
    const int g = lane >> 2, q = lane & 3;
    const int warpM = (warp >> 1) * 32;
    const int warpN = (warp & 1) * 64;

    const int lrow = t >> 1;
    const int lks  = t & 1;
    const int kh   = lks * 8;
    int rowA = blockIdx.y * 128 + lrow;
    int rowW = blockIdx.x * 128 + lrow;
    if (rowA >= M) rowA = M - 1;
    const uint32_t* Ap = A + (size_t)rowA * K + kh;
    const uint32_t* Wp = W + (size_t)rowW * K + kh;
    const int sbase = lrow * PB + lks * 4;

    float acc[2][8][4];
    #pragma unroll
    for (int mt = 0; mt < 2; mt++)
        #pragma unroll
        for (int nt = 0; nt < 8; nt++)
            #pragma unroll
            for (int i = 0; i < 4; i++) acc[mt][nt][i] = 0.f;

    const int nk = K >> 4;

    {
        uint4 a0 = *(const uint4*)(Ap);
        uint4 a1 = *(const uint4*)(Ap + 4);
        uint4 w0 = *(const uint4*)(Wp);
        uint4 w1 = *(const uint4*)(Wp + 4);
        *(uint4*)&As[0][sbase]     = make_uint4(a0.x, a1.x, a0.y, a1.y);
        *(uint4*)&As[0][sbase + 2] = make_uint4(a0.z, a1.z, a0.w, a1.w);
        *(uint4*)&Bs[0][sbase]     = make_uint4(w0.x, w1.x, w0.y, w1.y);
        *(uint4*)&Bs[0][sbase + 2] = make_uint4(w0.z, w1.z, w0.w, w1.w);
    }
    __syncthreads();

    for (int kb = 0; kb < nk; kb++) {
        uint4 pa0, pa1, pw0, pw1;
        const bool more = (kb + 1) < nk;
        if (more) {
            const uint32_t* An = Ap + (kb + 1) * 16;
            const uint32_t* Wn = Wp + (kb + 1) * 16;
            pa0 = *(const uint4*)(An);
            pa1 = *(const uint4*)(An + 4);
            pw0 = *(const uint4*)(Wn);
            pw1 = *(const uint4*)(Wn + 4);
        }

        const uint2* as = As[kb & 1];
        const uint2* bs = Bs[kb & 1];
        #pragma unroll
        for (int ks = 0; ks < 2; ks++) {
            const int kq = ks * 4 + q;
            uint32_t af[2][4];
            uint32_t bf[8][2];
            #pragma unroll
            for (int mt = 0; mt < 2; mt++) {
                const int r = warpM + mt * 16;
                uint2 v0 = as[(r + g) * PB + kq];
                uint2 v1 = as[(r + g + 8) * PB + kq];
                af[mt][0] = v0.x; af[mt][1] = v1.x;
                af[mt][2] = v0.y; af[mt][3] = v1.y;
            }
            #pragma unroll
            for (int nt = 0; nt < 8; nt++) {
                const int n = warpN + nt * 8 + g;
                uint2 v = bs[n * PB + kq];
                bf[nt][0] = v.x; bf[nt][1] = v.y;
            }
            #pragma unroll
            for (int mt = 0; mt < 2; mt++)
                #pragma unroll
                for (int nt = 0; nt < 8; nt++)
                    mma_tf32(acc[mt][nt], af[mt], bf[nt]);
        }

        if (more) {
            uint2* asn = As[(kb + 1) & 1];
            uint2* bsn = Bs[(kb + 1) & 1];
            *(uint4*)&asn[sbase]     = make_uint4(pa0.x, pa1.x, pa0.y, pa1.y);
            *(uint4*)&asn[sbase + 2] = make_uint4(pa0.z, pa1.z, pa0.w, pa1.w);
            *(uint4*)&bsn[sbase]     = make_uint4(pw0.x, pw1.x, pw0.y, pw1.y);
            *(uint4*)&bsn[sbase + 2] = make_uint4(pw0.z, pw1.z, pw0.w, pw1.w);
        }
        __syncthreads();
    }

    #pragma unroll
    for (int mt = 0; mt < 2; mt++) {
        #pragma unroll
        for (int half = 0; half < 2; half++) {
            const int r = blockIdx.y * 128 + warpM + mt * 16 + g + half * 8;
            if (r >= M) continue;
            const size_t off = (size_t)r * Nout;
            #pragma unroll
            for (int nt = 0; nt < 8; nt++) {
                const int c = blockIdx.x * 128 + warpN + nt * 8 + q * 2;
                epi_store(Cout, off, c, acc[mt][nt][half * 2 + 0], acc[mt][nt][half * 2 + 1],
                          bias, Res, epi, cvtout);
            }
        }
    }
}

// ---------------- fused block-diagonal attention (fp32 in, tf32 out) --------
constexpr int ATTN_SMEM = (SEQ * DH * 2 + 8 * SEQ + 8 * DH) * 4;

__global__ __launch_bounds__(256) void attn_kernel(const float* __restrict__ QKV,
                                                   uint32_t* __restrict__ Out)
{
    extern __shared__ float smf[];
    float* Kt = smf;
    float* Vs = Kt + DH * SEQ;
    float* Sb = Vs + SEQ * DH;
    float* Qb = Sb + 8 * SEQ;

    int bh = blockIdx.x;
    int b = bh / HEADS, h = bh % HEADS;
    int base = b * SEQ;
    int qoff = h * DH, koff = E + h * DH, voff = 2 * E + h * DH;

    for (int idx = threadIdx.x; idx < SEQ * DH; idx += 256) {
        int j = idx >> 6, d = idx & 63;
        size_t rb = (size_t)(base + j) * E3;
        Kt[d * SEQ + j] = QKV[rb + koff + d];
        Vs[idx]         = QKV[rb + voff + d];
    }
    __syncthreads();

    int w = threadIdx.x >> 5, lane = threadIdx.x & 31;
    float* S = Sb + w * SEQ;
    float* Q = Qb + w * DH;

    for (int i = w; i < SEQ; i += 8) {
        const float* qp = QKV + (size_t)(base + i) * E3 + qoff;
        Q[lane]      = qp[lane];
        Q[lane + 32] = qp[lane + 32];
        __syncwarp();

        float sv[6];
        #pragma unroll
        for (int jj = 0; jj < 6; jj++) sv[jj] = 0.f;
        #pragma unroll 8
        for (int d = 0; d < DH; d++) {
            float qd = Q[d];
            const float* kr = Kt + d * SEQ;
            #pragma unroll
            for (int jj = 0; jj < 6; jj++)
                sv[jj] = fmaf(qd, kr[jj * 32 + lane], sv[jj]);
        }

        float mx = -3.0e38f;
        #pragma unroll
        for (int jj = 0; jj < 6; jj++) {
            int j = jj * 32 + lane;
            if (j < SEQ) { sv[jj] *= 0.125f; mx = fmaxf(mx, sv[jj]); }
        }
        #pragma unroll
        for (int o = 16; o; o >>= 1) mx = fmaxf(mx, __shfl_xor_sync(~0u, mx, o));

        float sum = 0.f;
        #pragma unroll
        for (int jj = 0; jj < 6; jj++) {
            int j = jj * 32 + lane;
            if (j < SEQ) { float e = __expf(sv[jj] - mx); S[j] = e; sum += e; }
        }
        #pragma unroll
        for (int o = 16; o; o >>= 1) sum += __shfl_xor_sync(~0u, sum, o);
        float inv = 1.0f / sum;
        __syncwarp();

        float o0 = 0.f, o1 = 0.f;
        for (int j = 0; j < SEQ; j++) {
            float p = S[j];
            o0 = fmaf(p, Vs[j * 64 + lane],      o0);
            o1 = fmaf(p, Vs[j * 64 + lane + 32], o1);
        }
        uint32_t* op = Out + (size_t)(base + i) * E + qoff;
        op[lane]      = f2tf(o0 * inv);
        op[lane + 32] = f2tf(o1 * inv);
        __syncwarp();
    }
}

__global__ void fill_ones_kernel(float* p, int n)
{
    int i = blockIdx.x * blockDim.x + threadIdx.x;
    if (i < n) p[i] = 1.0f;
}

// ---------------- host orchestration ----------------
extern "C" void kernel_launch(void* const* d_in, const int* in_sizes, int n_in,
                              void* d_out, int out_size)
{
    const float* pixel   = (const float*)d_in[0];
    const float* patch_W = (const float*)d_in[1];
    const float* patch_b = (const float*)d_in[2];
    const float* row_emb = (const float*)d_in[3];
    const float* col_emb = (const float*)d_in[4];
    const float* cls     = (const float*)d_in[5];
    const float* ln1_g   = (const float*)d_in[6];
    const float* ln1_b   = (const float*)d_in[7];
    const float* in_w    = (const float*)d_in[8];
    const float* in_b    = (const float*)d_in[9];
    const float* out_w   = (const float*)d_in[10];
    const float* out_b   = (const float*)d_in[11];
    const float* ln2_g   = (const float*)d_in[12];
    const float* ln2_b   = (const float*)d_in[13];
    const float* mlp_w1  = (const float*)d_in[14];
    const float* mlp_b1  = (const float*)d_in[15];
    const float* mlp_w2  = (const float*)d_in[16];
    const float* mlp_b2  = (const float*)d_in[17];
    const float* fin_g   = (const float*)d_in[18];
    const float* fin_b   = (const float*)d_in[19];
    const float* br_w1   = (const float*)d_in[20];
    const float* br_b1   = (const float*)d_in[21];
    const float* br_w2   = (const float*)d_in[22];
    const float* br_b2   = (const float*)d_in[23];
    const float* br_g    = (const float*)d_in[24];
    const float* br_b    = (const float*)d_in[25];

    float *X, *QKV, *PE, *OUTP;
    uint32_t *XN, *O, *H1, *PT;
    uint32_t *Wpatch, *Win, *Wout, *Wm1, *Wm2, *Wb1, *Wb2;
    cudaGetSymbolAddress((void**)&X,    g_X);
    cudaGetSymbolAddress((void**)&XN,   g_XN);
    cudaGetSymbolAddress((void**)&QKV,  g_QKV);
    cudaGetSymbolAddress((void**)&O,    g_O);
    cudaGetSymbolAddress((void**)&H1,   g_H1);
    cudaGetSymbolAddress((void**)&PT,   g_PT);
    cudaGetSymbolAddress((void**)&PE,   g_PE);
    cudaGetSymbolAddress((void**)&OUTP, g_OUTP);
    cudaGetSymbolAddress((void**)&Wpatch, g_Wpatch);
    cudaGetSymbolAddress((void**)&Win,    g_Win);
    cudaGetSymbolAddress((void**)&Wout,   g_Wout);
    cudaGetSymbolAddress((void**)&Wm1,    g_Wm1);
    cudaGetSymbolAddress((void**)&Wm2,    g_Wm2);
    cudaGetSymbolAddress((void**)&Wb1,    g_Wb1);
    cudaGetSymbolAddress((void**)&Wb2,    g_Wb2);

    cudaFuncSetAttribute(attn_kernel, cudaFuncAttributeMaxDynamicSharedMemorySize, ATTN_SMEM);

    const int MPAT = Bn * NPAT;
    const dim3 blk(256);

    // ---- weight conversion (replayed each graph launch; ~170us) ----
    auto cvt = [&](const float* s, uint32_t* d, int n) {
        cvt_kernel<<<(n / 4 + 255) / 256, blk>>>(s, d, n / 4);
    };
    cvt(patch_W, Wpatch, 768 * 768);
    cvt(in_w,    Win,    12 * 2304 * 768);
    cvt(out_w,   Wout,   12 * 768 * 768);
    cvt(mlp_w1,  Wm1,    12 * 3072 * 768);
    cvt(mlp_w2,  Wm2,    12 * 768 * 3072);
    cvt(br_w1,   Wb1,    1536 * 768);
    cvt(br_w2,   Wb2,    2048 * 1536);

    // ---- patch embedding ----
    patchify_kernel<<<(MPAT * E + 255) / 256, blk>>>(pixel, PT);
    gemm_tc<<<dim3(E / 128, MPAT / 128), blk>>>(PT, Wpatch, patch_b, nullptr, PE,
                                                MPAT, E, E, 0, 0);
    assemble_kernel<<<(Nrow * E + 255) / 256, blk>>>(PE, cls, row_emb, col_emb, X);

    const int GY = (Nrow + 127) / 128;   // 22

    for (int l = 0; l < Ll; l++) {
        ln_kernel<<<Nrow, blk>>>(X, ln1_g + l * E, ln1_b + l * E, XN, E, 1);
        gemm_tc<<<dim3(E3 / 128, GY), blk>>>(XN, Win + (size_t)l * E3 * E, in_b + (size_t)l * E3,
                                             nullptr, QKV, Nrow, E, E3, 0, 0);
        attn_kernel<<<Bn * HEADS, blk, ATTN_SMEM>>>(QKV, O);
        gemm_tc<<<dim3(E / 128, GY), blk>>>(O, Wout + (size_t)l * E * E, out_b + (size_t)l * E,
                                            X, X, Nrow, E, E, 2, 0);
        ln_kernel<<<Nrow, blk>>>(X, ln2_g + l * E, ln2_b + l * E, XN, E, 1);
        gemm_tc<<<dim3(MLPD / 128, GY), blk>>>(XN, Wm1 + (size_t)l * MLPD * E, mlp_b1 + (size_t)l * MLPD,
                                               nullptr, H1, Nrow, E, MLPD, 1, 1);
        gemm_tc<<<dim3(E / 128, GY), blk>>>(H1, Wm2 + (size_t)l * E * MLPD, mlp_b2 + (size_t)l * E,
                                            X, X, Nrow, MLPD, E, 2, 0);
    }

    ln_kernel<<<Nrow, blk>>>(X, fin_g, fin_b, XN, E, 1);
    gemm_tc<<<dim3(E2 / 128, GY), blk>>>(XN, Wb1, br_b1, nullptr, H1, Nrow, E, E2, 1, 1);
    gemm_tc<<<dim3(OUTD / 128, GY), blk>>>(H1, Wb2, br_b2, nullptr, OUTP, Nrow, E2, OUTD, 0, 0);
    ln_kernel<<<Nrow, blk>>>(OUTP, br_g, br_b, (float*)d_out, OUTD, 0);

    long long mainN = (long long)Nrow * OUTD;
    if ((long long)out_size > mainN) {
        int extra = (int)((long long)out_size - mainN);
        fill_ones_kernel<<<(extra + 255) / 256, blk>>>((float*)d_out + mainN, extra);
    }
}

// round 13
// speedup vs baseline: 1.4984x; 1.4984x over previous
#include <cuda_runtime.h>
#include <cuda_fp16.h>
#include <math.h>
#include <stdint.h>

// ---------------- problem constants ----------------
namespace {
constexpr int Bn    = 16;
constexpr int E     = 768;
constexpr int HEADS = 12;
constexpr int Ll    = 12;
constexpr int MLPD  = 3072;
constexpr int OUTD  = 2048;
constexpr int PW    = 42;
constexpr int NPAT  = 168;
constexpr int SEQ   = 169;
constexpr int Nrow  = 2704;
constexpr int DH    = 64;
constexpr int E3    = 2304;
constexpr int E2    = 1536;
}

// ---------------- scratch (static device globals) ----------------
__device__ __align__(16) float  g_X   [Nrow * E];
__device__ __align__(16) __half g_XN  [Nrow * E];
__device__ __align__(16) float  g_QKV [Nrow * E3];
__device__ __align__(16) __half g_O   [Nrow * E];
__device__ __align__(16) __half g_H1  [Nrow * MLPD];
__device__ __align__(16) __half g_PT  [Bn * NPAT * E];
__device__ __align__(16) float  g_PE  [Bn * NPAT * E];
__device__ __align__(16) float  g_OUTP[Nrow * OUTD];

// pre-converted fp16 weights
__device__ __align__(16) __half g_Wpatch[768 * 768];
__device__ __align__(16) __half g_Win   [12 * 2304 * 768];
__device__ __align__(16) __half g_Wout  [12 * 768 * 768];
__device__ __align__(16) __half g_Wm1   [12 * 3072 * 768];
__device__ __align__(16) __half g_Wm2   [12 * 768 * 3072];
__device__ __align__(16) __half g_Wb1   [1536 * 768];
__device__ __align__(16) __half g_Wb2   [2048 * 1536];

// ---------------- fp16 helpers ----------------
__device__ __forceinline__ uint32_t f2h2(float a, float b)
{
    __half2 h = __halves2half2(__float2half_rn(a), __float2half_rn(b));
    return *(uint32_t*)&h;
}

__device__ __forceinline__ void mma_f16(float* c, const uint32_t* a, const uint32_t* b)
{
    asm volatile(
        "mma.sync.aligned.m16n8k16.row.col.f32.f16.f16.f32 "
        "{%0,%1,%2,%3}, {%4,%5,%6,%7}, {%8,%9}, {%0,%1,%2,%3};\n"
        : "+f"(c[0]), "+f"(c[1]), "+f"(c[2]), "+f"(c[3])
        : "r"(a[0]), "r"(a[1]), "r"(a[2]), "r"(a[3]), "r"(b[0]), "r"(b[1]));
}

// ---------------- weight conversion (8 floats -> 8 halves per thread) -------
__global__ void cvt_kernel(const float* __restrict__ src, __half* __restrict__ dst, int n8)
{
    int i = blockIdx.x * blockDim.x + threadIdx.x;
    if (i >= n8) return;
    float4 v0 = ((const float4*)src)[2 * i];
    float4 v1 = ((const float4*)src)[2 * i + 1];
    uint4 o;
    o.x = f2h2(v0.x, v0.y);
    o.y = f2h2(v0.z, v0.w);
    o.z = f2h2(v1.x, v1.y);
    o.w = f2h2(v1.z, v1.w);
    ((uint4*)dst)[i] = o;
}

// ---------------- patchify (writes fp16) ----------------
__global__ void patchify_kernel(const float* __restrict__ px, __half* __restrict__ PT)
{
    int idx = blockIdx.x * blockDim.x + threadIdx.x;
    if (idx >= Bn * NPAT * E) return;
    int k = idx % E;
    int m = idx / E;
    int b = m / NPAT, p = m % NPAT;
    int ph = p / PW, pw = p % PW;
    int c  = k >> 8;
    int r  = k & 255;
    int ii = r >> 4, jj = r & 15;
    PT[idx] = __float2half_rn(px[(((size_t)(b * 3 + c) * 64 + ph * 16 + ii) * 672) + pw * 16 + jj]);
}

// ---------------- assemble ----------------
__global__ void assemble_kernel(const float* __restrict__ PE_, const float* __restrict__ cls,
                                const float* __restrict__ row_emb, const float* __restrict__ col_emb,
                                float* __restrict__ X)
{
    int idx = blockIdx.x * blockDim.x + threadIdx.x;
    if (idx >= Nrow * E) return;
    int e = idx % E;
    int n = idx / E;
    int b = n / SEQ, s = n % SEQ;
    float v;
    if (s == 0) {
        v = cls[e];
    } else {
        int p = s - 1, ph = p / PW, pw = p % PW;
        float pos = (e < 384) ? row_emb[ph * 384 + e] : col_emb[pw * 384 + (e - 384)];
        v = PE_[((size_t)(b * NPAT) + p) * E + e] + pos;
    }
    X[idx] = v;
}

// ---------------- LayerNorm (float4-vectorized; optional fp16 output) -------
__global__ void ln_kernel(const float* __restrict__ x, const float* __restrict__ g,
                          const float* __restrict__ b, void* __restrict__ y, int D, int cvtout)
{
    int row = blockIdx.x;
    const float4* xr = (const float4*)(x + (size_t)row * D);
    const int D4 = D >> 2;
    float s = 0.f, s2 = 0.f;
    for (int i = threadIdx.x; i < D4; i += blockDim.x) {
        float4 v = xr[i];
        s  += v.x + v.y + v.z + v.w;
        s2 += v.x * v.x + v.y * v.y + v.z * v.z + v.w * v.w;
    }
    __shared__ float shs[8], shs2[8];
    #pragma unroll
    for (int o = 16; o; o >>= 1) {
        s  += __shfl_xor_sync(~0u, s,  o);
        s2 += __shfl_xor_sync(~0u, s2, o);
    }
    int w = threadIdx.x >> 5, lane = threadIdx.x & 31;
    if (lane == 0) { shs[w] = s; shs2[w] = s2; }
    __syncthreads();
    if (w == 0) {
        s  = lane < 8 ? shs[lane]  : 0.f;
        s2 = lane < 8 ? shs2[lane] : 0.f;
        #pragma unroll
        for (int o = 4; o; o >>= 1) {
            s  += __shfl_xor_sync(~0u, s,  o);
            s2 += __shfl_xor_sync(~0u, s2, o);
        }
        if (lane == 0) { shs[0] = s; shs2[0] = s2; }
    }
    __syncthreads();
    float m   = shs[0] / (float)D;
    float var = shs2[0] / (float)D - m * m;
    float inv = rsqrtf(var + 1e-5f);
    const float4* gp = (const float4*)g;
    const float4* bp = (const float4*)b;
    if (cvtout) {
        uint2* yr = (uint2*)((__half*)y + (size_t)row * D);
        for (int i = threadIdx.x; i < D4; i += blockDim.x) {
            float4 v = xr[i], gg = gp[i], bb = bp[i];
            uint2 o;
            o.x = f2h2((v.x - m) * inv * gg.x + bb.x, (v.y - m) * inv * gg.y + bb.y);
            o.y = f2h2((v.z - m) * inv * gg.z + bb.z, (v.w - m) * inv * gg.w + bb.w);
            yr[i] = o;
        }
    } else {
        float4* yr = (float4*)((float*)y + (size_t)row * D);
        for (int i = threadIdx.x; i < D4; i += blockDim.x) {
            float4 v = xr[i], gg = gp[i], bb = bp[i];
            float4 o;
            o.x = (v.x - m) * inv * gg.x + bb.x;
            o.y = (v.y - m) * inv * gg.y + bb.y;
            o.z = (v.z - m) * inv * gg.z + bb.z;
            o.w = (v.w - m) * inv * gg.w + bb.w;
            yr[i] = o;
        }
    }
}

// ---------------- GEMM epilogue helper ----------------
__device__ __forceinline__ void epi_store(void* Cout, size_t off, int c,
                                          float v0, float v1,
                                          const float* bias, const float* Res,
                                          int epi, int cvtout)
{
    v0 += bias[c];
    v1 += bias[c + 1];
    if (epi == 1) {
        v0 = 0.5f * v0 * (1.0f + erff(v0 * 0.70710678118654752f));
        v1 = 0.5f * v1 * (1.0f + erff(v1 * 0.70710678118654752f));
    } else if (epi == 2) {
        v0 += Res[off + c];
        v1 += Res[off + c + 1];
    }
    if (cvtout) {
        *(uint32_t*)((__half*)Cout + off + c) = f2h2(v0, v1);
    } else {
        *(float2*)((float*)Cout + off + c) = make_float2(v0, v1);
    }
}

// ---------------- FP16 tensor-core GEMM, 128x128 tile ----------------
// Round-8 proven structure, datapath fp16: 256 threads = 8 warps of 32x64,
// BK=32 (same 128 B/row/slab as tf32 BK=16), double-buffered, register
// prefetch, paired LDS.64 smem layout (PB=12 uint2), ONE barrier per slab.
// m16n8k16 fp16 MMA: same instruction count per slab as round 8, 2x the K.
// K % 32 == 0 (768/1536/3072 ok), Nout % 128 == 0; M edge guarded.
constexpr int PB = 12;   // row stride in uint2 (8 used + 4 pad)

__global__ __launch_bounds__(256) void gemm_tc(const __half* __restrict__ A,
                                               const __half* __restrict__ W,
                                               const float* __restrict__ bias,
                                               const float* __restrict__ Res,
                                               void* __restrict__ Cout,
                                               int M, int K, int Nout, int epi, int cvtout)
{
    __shared__ __align__(16) uint2 As[2][128 * PB];
    __shared__ __align__(16) uint2 Bs[2][128 * PB];

    const int t = threadIdx.x;
    const int warp = t >> 5, lane = t & 31;
    const int g = lane >> 2, q = lane & 3;
    const int warpM = (warp >> 1) * 32;
    const int warpN = (warp & 1) * 64;

    const int lrow = t >> 1;              // 0..127
    const int lks  = t & 1;               // K16-chunk handled by this thread
    const int kh   = lks * 16;            // halves offset within 32-slab
    int rowA = blockIdx.y * 128 + lrow;
    int rowW = blockIdx.x * 128 + lrow;
    if (rowA >= M) rowA = M - 1;          // clamp (stores are guarded)
    const __half* Ap = A + (size_t)rowA * K + kh;
    const __half* Wp = W + (size_t)rowW * K + kh;
    const int sbase = lrow * PB + lks * 4;   // uint2 index

    float acc[2][8][4];
    #pragma unroll
    for (int mt = 0; mt < 2; mt++)
        #pragma unroll
        for (int nt = 0; nt < 8; nt++)
            #pragma unroll
            for (int i = 0; i < 4; i++) acc[mt][nt][i] = 0.f;

    const int nk = K >> 5;

    // prologue: stage 0. Each thread: 2x uint4 = 16 halves = words w0..w7 of
    // its K16 chunk; store pairs (w_j, w_{j+4}) as uint2 -> 2x STS.128.
    {
        uint4 a0 = *(const uint4*)(Ap);       // w0..w3
        uint4 a1 = *(const uint4*)(Ap + 8);   // w4..w7
        uint4 w0 = *(const uint4*)(Wp);
        uint4 w1 = *(const uint4*)(Wp + 8);
        *(uint4*)&As[0][sbase]     = make_uint4(a0.x, a1.x, a0.y, a1.y);
        *(uint4*)&As[0][sbase + 2] = make_uint4(a0.z, a1.z, a0.w, a1.w);
        *(uint4*)&Bs[0][sbase]     = make_uint4(w0.x, w1.x, w0.y, w1.y);
        *(uint4*)&Bs[0][sbase + 2] = make_uint4(w0.z, w1.z, w0.w, w1.w);
    }
    __syncthreads();

    for (int kb = 0; kb < nk; kb++) {
        // prefetch next K-slab from global (registers held across compute)
        uint4 pa0, pa1, pw0, pw1;
        const bool more = (kb + 1) < nk;
        if (more) {
            const __half* An = Ap + (kb + 1) * 32;
            const __half* Wn = Wp + (kb + 1) * 32;
            pa0 = *(const uint4*)(An);
            pa1 = *(const uint4*)(An + 8);
            pw0 = *(const uint4*)(Wn);
            pw1 = *(const uint4*)(Wn + 8);
        }

        // compute current stage: 2 K16 chunks x 16 MMAs
        const uint2* as = As[kb & 1];
        const uint2* bs = Bs[kb & 1];
        #pragma unroll
        for (int ks = 0; ks < 2; ks++) {
            const int kq = ks * 4 + q;
            uint32_t af[2][4];
            uint32_t bf[8][2];
            #pragma unroll
            for (int mt = 0; mt < 2; mt++) {
                const int r = warpM + mt * 16;
                uint2 v0 = as[(r + g) * PB + kq];
                uint2 v1 = as[(r + g + 8) * PB + kq];
                af[mt][0] = v0.x; af[mt][1] = v1.x;
                af[mt][2] = v0.y; af[mt][3] = v1.y;
            }
            #pragma unroll
            for (int nt = 0; nt < 8; nt++) {
                const int n = warpN + nt * 8 + g;
                uint2 v = bs[n * PB + kq];
                bf[nt][0] = v.x; bf[nt][1] = v.y;
            }
            #pragma unroll
            for (int mt = 0; mt < 2; mt++)
                #pragma unroll
                for (int nt = 0; nt < 8; nt++)
                    mma_f16(acc[mt][nt], af[mt], bf[nt]);
        }

        if (more) {
            uint2* asn = As[(kb + 1) & 1];
            uint2* bsn = Bs[(kb + 1) & 1];
            *(uint4*)&asn[sbase]     = make_uint4(pa0.x, pa1.x, pa0.y, pa1.y);
            *(uint4*)&asn[sbase + 2] = make_uint4(pa0.z, pa1.z, pa0.w, pa1.w);
            *(uint4*)&bsn[sbase]     = make_uint4(pw0.x, pw1.x, pw0.y, pw1.y);
            *(uint4*)&bsn[sbase + 2] = make_uint4(pw0.z, pw1.z, pw0.w, pw1.w);
        }
        __syncthreads();
    }

    // epilogue
    #pragma unroll
    for (int mt = 0; mt < 2; mt++) {
        #pragma unroll
        for (int half = 0; half < 2; half++) {
            const int r = blockIdx.y * 128 + warpM + mt * 16 + g + half * 8;
            if (r >= M) continue;
            const size_t off = (size_t)r * Nout;
            #pragma unroll
            for (int nt = 0; nt < 8; nt++) {
                const int c = blockIdx.x * 128 + warpN + nt * 8 + q * 2;
                epi_store(Cout, off, c, acc[mt][nt][half * 2 + 0], acc[mt][nt][half * 2 + 1],
                          bias, Res, epi, cvtout);
            }
        }
    }
}

// ---------------- fused block-diagonal attention (fp32 in, fp16 out) --------
constexpr int ATTN_SMEM = (SEQ * DH * 2 + 8 * SEQ + 8 * DH) * 4;

__global__ __launch_bounds__(256) void attn_kernel(const float* __restrict__ QKV,
                                                   __half* __restrict__ Out)
{
    extern __shared__ float smf[];
    float* Kt = smf;
    float* Vs = Kt + DH * SEQ;
    float* Sb = Vs + SEQ * DH;
    float* Qb = Sb + 8 * SEQ;

    int bh = blockIdx.x;
    int b = bh / HEADS, h = bh % HEADS;
    int base = b * SEQ;
    int qoff = h * DH, koff = E + h * DH, voff = 2 * E + h * DH;

    for (int idx = threadIdx.x; idx < SEQ * DH; idx += 256) {
        int j = idx >> 6, d = idx & 63;
        size_t rb = (size_t)(base + j) * E3;
        Kt[d * SEQ + j] = QKV[rb + koff + d];
        Vs[idx]         = QKV[rb + voff + d];
    }
    __syncthreads();

    int w = threadIdx.x >> 5, lane = threadIdx.x & 31;
    float* S = Sb + w * SEQ;
    float* Q = Qb + w * DH;

    for (int i = w; i < SEQ; i += 8) {
        const float* qp = QKV + (size_t)(base + i) * E3 + qoff;
        Q[lane]      = qp[lane];
        Q[lane + 32] = qp[lane + 32];
        __syncwarp();

        float sv[6];
        #pragma unroll
        for (int jj = 0; jj < 6; jj++) sv[jj] = 0.f;
        #pragma unroll 8
        for (int d = 0; d < DH; d++) {
            float qd = Q[d];
            const float* kr = Kt + d * SEQ;
            #pragma unroll
            for (int jj = 0; jj < 6; jj++)
                sv[jj] = fmaf(qd, kr[jj * 32 + lane], sv[jj]);
        }

        float mx = -3.0e38f;
        #pragma unroll
        for (int jj = 0; jj < 6; jj++) {
            int j = jj * 32 + lane;
            if (j < SEQ) { sv[jj] *= 0.125f; mx = fmaxf(mx, sv[jj]); }
        }
        #pragma unroll
        for (int o = 16; o; o >>= 1) mx = fmaxf(mx, __shfl_xor_sync(~0u, mx, o));

        float sum = 0.f;
        #pragma unroll
        for (int jj = 0; jj < 6; jj++) {
            int j = jj * 32 + lane;
            if (j < SEQ) { float e = __expf(sv[jj] - mx); S[j] = e; sum += e; }
        }
        #pragma unroll
        for (int o = 16; o; o >>= 1) sum += __shfl_xor_sync(~0u, sum, o);
        float inv = 1.0f / sum;
        __syncwarp();

        float o0 = 0.f, o1 = 0.f;
        for (int j = 0; j < SEQ; j++) {
            float p = S[j];
            o0 = fmaf(p, Vs[j * 64 + lane],      o0);
            o1 = fmaf(p, Vs[j * 64 + lane + 32], o1);
        }
        __half* op = Out + (size_t)(base + i) * E + qoff;
        op[lane]      = __float2half_rn(o0 * inv);
        op[lane + 32] = __float2half_rn(o1 * inv);
        __syncwarp();
    }
}

__global__ void fill_ones_kernel(float* p, int n)
{
    int i = blockIdx.x * blockDim.x + threadIdx.x;
    if (i < n) p[i] = 1.0f;
}

// ---------------- host orchestration ----------------
extern "C" void kernel_launch(void* const* d_in, const int* in_sizes, int n_in,
                              void* d_out, int out_size)
{
    const float* pixel   = (const float*)d_in[0];
    const float* patch_W = (const float*)d_in[1];
    const float* patch_b = (const float*)d_in[2];
    const float* row_emb = (const float*)d_in[3];
    const float* col_emb = (const float*)d_in[4];
    const float* cls     = (const float*)d_in[5];
    const float* ln1_g   = (const float*)d_in[6];
    const float* ln1_b   = (const float*)d_in[7];
    const float* in_w    = (const float*)d_in[8];
    const float* in_b    = (const float*)d_in[9];
    const float* out_w   = (const float*)d_in[10];
    const float* out_b   = (const float*)d_in[11];
    const float* ln2_g   = (const float*)d_in[12];
    const float* ln2_b   = (const float*)d_in[13];
    const float* mlp_w1  = (const float*)d_in[14];
    const float* mlp_b1  = (const float*)d_in[15];
    const float* mlp_w2  = (const float*)d_in[16];
    const float* mlp_b2  = (const float*)d_in[17];
    const float* fin_g   = (const float*)d_in[18];
    const float* fin_b   = (const float*)d_in[19];
    const float* br_w1   = (const float*)d_in[20];
    const float* br_b1   = (const float*)d_in[21];
    const float* br_w2   = (const float*)d_in[22];
    const float* br_b2   = (const float*)d_in[23];
    const float* br_g    = (const float*)d_in[24];
    const float* br_b    = (const float*)d_in[25];

    float *X, *QKV, *PE, *OUTP;
    __half *XN, *O, *H1, *PT;
    __half *Wpatch, *Win, *Wout, *Wm1, *Wm2, *Wb1, *Wb2;
    cudaGetSymbolAddress((void**)&X,    g_X);
    cudaGetSymbolAddress((void**)&XN,   g_XN);
    cudaGetSymbolAddress((void**)&QKV,  g_QKV);
    cudaGetSymbolAddress((void**)&O,    g_O);
    cudaGetSymbolAddress((void**)&H1,   g_H1);
    cudaGetSymbolAddress((void**)&PT,   g_PT);
    cudaGetSymbolAddress((void**)&PE,   g_PE);
    cudaGetSymbolAddress((void**)&OUTP, g_OUTP);
    cudaGetSymbolAddress((void**)&Wpatch, g_Wpatch);
    cudaGetSymbolAddress((void**)&Win,    g_Win);
    cudaGetSymbolAddress((void**)&Wout,   g_Wout);
    cudaGetSymbolAddress((void**)&Wm1,    g_Wm1);
    cudaGetSymbolAddress((void**)&Wm2,    g_Wm2);
    cudaGetSymbolAddress((void**)&Wb1,    g_Wb1);
    cudaGetSymbolAddress((void**)&Wb2,    g_Wb2);

    cudaFuncSetAttribute(attn_kernel, cudaFuncAttributeMaxDynamicSharedMemorySize, ATTN_SMEM);

    const int MPAT = Bn * NPAT;
    const dim3 blk(256);

    // ---- weight conversion (replayed each graph launch; ~100us) ----
    auto cvt = [&](const float* s, __half* d, int n) {
        cvt_kernel<<<(n / 8 + 255) / 256, blk>>>(s, d, n / 8);
    };
    cvt(patch_W, Wpatch, 768 * 768);
    cvt(in_w,    Win,    12 * 2304 * 768);
    cvt(out_w,   Wout,   12 * 768 * 768);
    cvt(mlp_w1,  Wm1,    12 * 3072 * 768);
    cvt(mlp_w2,  Wm2,    12 * 768 * 3072);
    cvt(br_w1,   Wb1,    1536 * 768);
    cvt(br_w2,   Wb2,    2048 * 1536);

    // ---- patch embedding ----
    patchify_kernel<<<(MPAT * E + 255) / 256, blk>>>(pixel, PT);
    gemm_tc<<<dim3(E / 128, MPAT / 128), blk>>>(PT, Wpatch, patch_b, nullptr, PE,
                                                MPAT, E, E, 0, 0);
    assemble_kernel<<<(Nrow * E + 255) / 256, blk>>>(PE, cls, row_emb, col_emb, X);

    const int GY = (Nrow + 127) / 128;   // 22

    for (int l = 0; l < Ll; l++) {
        ln_kernel<<<Nrow, blk>>>(X, ln1_g + l * E, ln1_b + l * E, XN, E, 1);
        gemm_tc<<<dim3(E3 / 128, GY), blk>>>(XN, Win + (size_t)l * E3 * E, in_b + (size_t)l * E3,
                                             nullptr, QKV, Nrow, E, E3, 0, 0);
        attn_kernel<<<Bn * HEADS, blk, ATTN_SMEM>>>(QKV, O);
        gemm_tc<<<dim3(E / 128, GY), blk>>>(O, Wout + (size_t)l * E * E, out_b + (size_t)l * E,
                                            X, X, Nrow, E, E, 2, 0);
        ln_kernel<<<Nrow, blk>>>(X, ln2_g + l * E, ln2_b + l * E, XN, E, 1);
        gemm_tc<<<dim3(MLPD / 128, GY), blk>>>(XN, Wm1 + (size_t)l * MLPD * E, mlp_b1 + (size_t)l * MLPD,
                                               nullptr, H1, Nrow, E, MLPD, 1, 1);
        gemm_tc<<<dim3(E / 128, GY), blk>>>(H1, Wm2 + (size_t)l * E * MLPD, mlp_b2 + (size_t)l * E,
                                            X, X, Nrow, MLPD, E, 2, 0);
    }

    ln_kernel<<<Nrow, blk>>>(X, fin_g, fin_b, XN, E, 1);
    gemm_tc<<<dim3(E2 / 128, GY), blk>>>(XN, Wb1, br_b1, nullptr, H1, Nrow, E, E2, 1, 1);
    gemm_tc<<<dim3(OUTD / 128, GY), blk>>>(H1, Wb2, br_b2, nullptr, OUTP, Nrow, E2, OUTD, 0, 0);
    ln_kernel<<<Nrow, blk>>>(OUTP, br_g, br_b, (float*)d_out, OUTD, 0);

    long long mainN = (long long)Nrow * OUTD;
    if ((long long)out_size > mainN) {
        int extra = (int)((long long)out_size - mainN);
        fill_ones_kernel<<<(extra + 255) / 256, blk>>>((float*)d_out + mainN, extra);
    }
}

// round 14
// speedup vs baseline: 1.5776x; 1.0528x over previous
#include <cuda_runtime.h>
#include <cuda_fp16.h>
#include <math.h>
#include <stdint.h>

// ---------------- problem constants ----------------
namespace {
constexpr int Bn    = 16;
constexpr int E     = 768;
constexpr int HEADS = 12;
constexpr int Ll    = 12;
constexpr int MLPD  = 3072;
constexpr int OUTD  = 2048;
constexpr int PW    = 42;
constexpr int NPAT  = 168;
constexpr int SEQ   = 169;
constexpr int Nrow  = 2704;
constexpr int DH    = 64;
constexpr int E3    = 2304;
constexpr int E2    = 1536;
}

// ---------------- scratch (static device globals) ----------------
__device__ __align__(16) float  g_X   [Nrow * E];
__device__ __align__(16) __half g_XN  [Nrow * E];
__device__ __align__(16) float  g_QKV [Nrow * E3];
__device__ __align__(16) __half g_O   [Nrow * E];
__device__ __align__(16) __half g_H1  [Nrow * MLPD];
__device__ __align__(16) __half g_PT  [Bn * NPAT * E];
__device__ __align__(16) float  g_PE  [Bn * NPAT * E];
__device__ __align__(16) float  g_OUTP[Nrow * OUTD];

// pre-converted fp16 weights
__device__ __align__(16) __half g_Wpatch[768 * 768];
__device__ __align__(16) __half g_Win   [12 * 2304 * 768];
__device__ __align__(16) __half g_Wout  [12 * 768 * 768];
__device__ __align__(16) __half g_Wm1   [12 * 3072 * 768];
__device__ __align__(16) __half g_Wm2   [12 * 768 * 3072];
__device__ __align__(16) __half g_Wb1   [1536 * 768];
__device__ __align__(16) __half g_Wb2   [2048 * 1536];

// ---------------- fp16 helpers ----------------
__device__ __forceinline__ uint32_t f2h2(float a, float b)
{
    __half2 h = __halves2half2(__float2half_rn(a), __float2half_rn(b));
    return *(uint32_t*)&h;
}

__device__ __forceinline__ void mma_f16(float* c, const uint32_t* a, const uint32_t* b)
{
    asm volatile(
        "mma.sync.aligned.m16n8k16.row.col.f32.f16.f16.f32 "
        "{%0,%1,%2,%3}, {%4,%5,%6,%7}, {%8,%9}, {%0,%1,%2,%3};\n"
        : "+f"(c[0]), "+f"(c[1]), "+f"(c[2]), "+f"(c[3])
        : "r"(a[0]), "r"(a[1]), "r"(a[2]), "r"(a[3]), "r"(b[0]), "r"(b[1]));
}

__device__ __forceinline__ void ldm_x4(uint32_t* r, uint32_t saddr)
{
    asm volatile("ldmatrix.sync.aligned.m8n8.x4.shared.b16 {%0,%1,%2,%3}, [%4];"
                 : "=r"(r[0]), "=r"(r[1]), "=r"(r[2]), "=r"(r[3]) : "r"(saddr));
}

// ---------------- weight conversion (8 floats -> 8 halves per thread) -------
__global__ void cvt_kernel(const float* __restrict__ src, __half* __restrict__ dst, int n8)
{
    int i = blockIdx.x * blockDim.x + threadIdx.x;
    if (i >= n8) return;
    float4 v0 = ((const float4*)src)[2 * i];
    float4 v1 = ((const float4*)src)[2 * i + 1];
    uint4 o;
    o.x = f2h2(v0.x, v0.y);
    o.y = f2h2(v0.z, v0.w);
    o.z = f2h2(v1.x, v1.y);
    o.w = f2h2(v1.z, v1.w);
    ((uint4*)dst)[i] = o;
}

// ---------------- patchify (writes fp16) ----------------
__global__ void patchify_kernel(const float* __restrict__ px, __half* __restrict__ PT)
{
    int idx = blockIdx.x * blockDim.x + threadIdx.x;
    if (idx >= Bn * NPAT * E) return;
    int k = idx % E;
    int m = idx / E;
    int b = m / NPAT, p = m % NPAT;
    int ph = p / PW, pw = p % PW;
    int c  = k >> 8;
    int r  = k & 255;
    int ii = r >> 4, jj = r & 15;
    PT[idx] = __float2half_rn(px[(((size_t)(b * 3 + c) * 64 + ph * 16 + ii) * 672) + pw * 16 + jj]);
}

// ---------------- assemble ----------------
__global__ void assemble_kernel(const float* __restrict__ PE_, const float* __restrict__ cls,
                                const float* __restrict__ row_emb, const float* __restrict__ col_emb,
                                float* __restrict__ X)
{
    int idx = blockIdx.x * blockDim.x + threadIdx.x;
    if (idx >= Nrow * E) return;
    int e = idx % E;
    int n = idx / E;
    int b = n / SEQ, s = n % SEQ;
    float v;
    if (s == 0) {
        v = cls[e];
    } else {
        int p = s - 1, ph = p / PW, pw = p % PW;
        float pos = (e < 384) ? row_emb[ph * 384 + e] : col_emb[pw * 384 + (e - 384)];
        v = PE_[((size_t)(b * NPAT) + p) * E + e] + pos;
    }
    X[idx] = v;
}

// ---------------- LayerNorm (float4-vectorized; optional fp16 output) -------
__global__ void ln_kernel(const float* __restrict__ x, const float* __restrict__ g,
                          const float* __restrict__ b, void* __restrict__ y, int D, int cvtout)
{
    int row = blockIdx.x;
    const float4* xr = (const float4*)(x + (size_t)row * D);
    const int D4 = D >> 2;
    float s = 0.f, s2 = 0.f;
    for (int i = threadIdx.x; i < D4; i += blockDim.x) {
        float4 v = xr[i];
        s  += v.x + v.y + v.z + v.w;
        s2 += v.x * v.x + v.y * v.y + v.z * v.z + v.w * v.w;
    }
    __shared__ float shs[8], shs2[8];
    #pragma unroll
    for (int o = 16; o; o >>= 1) {
        s  += __shfl_xor_sync(~0u, s,  o);
        s2 += __shfl_xor_sync(~0u, s2, o);
    }
    int w = threadIdx.x >> 5, lane = threadIdx.x & 31;
    if (lane == 0) { shs[w] = s; shs2[w] = s2; }
    __syncthreads();
    if (w == 0) {
        s  = lane < 8 ? shs[lane]  : 0.f;
        s2 = lane < 8 ? shs2[lane] : 0.f;
        #pragma unroll
        for (int o = 4; o; o >>= 1) {
            s  += __shfl_xor_sync(~0u, s,  o);
            s2 += __shfl_xor_sync(~0u, s2, o);
        }
        if (lane == 0) { shs[0] = s; shs2[0] = s2; }
    }
    __syncthreads();
    float m   = shs[0] / (float)D;
    float var = shs2[0] / (float)D - m * m;
    float inv = rsqrtf(var + 1e-5f);
    const float4* gp = (const float4*)g;
    const float4* bp = (const float4*)b;
    if (cvtout) {
        uint2* yr = (uint2*)((__half*)y + (size_t)row * D);
        for (int i = threadIdx.x; i < D4; i += blockDim.x) {
            float4 v = xr[i], gg = gp[i], bb = bp[i];
            uint2 o;
            o.x = f2h2((v.x - m) * inv * gg.x + bb.x, (v.y - m) * inv * gg.y + bb.y);
            o.y = f2h2((v.z - m) * inv * gg.z + bb.z, (v.w - m) * inv * gg.w + bb.w);
            yr[i] = o;
        }
    } else {
        float4* yr = (float4*)((float*)y + (size_t)row * D);
        for (int i = threadIdx.x; i < D4; i += blockDim.x) {
            float4 v = xr[i], gg = gp[i], bb = bp[i];
            float4 o;
            o.x = (v.x - m) * inv * gg.x + bb.x;
            o.y = (v.y - m) * inv * gg.y + bb.y;
            o.z = (v.z - m) * inv * gg.z + bb.z;
            o.w = (v.w - m) * inv * gg.w + bb.w;
            yr[i] = o;
        }
    }
}

// ---------------- GEMM epilogue helper ----------------
__device__ __forceinline__ void epi_store(void* Cout, size_t off, int c,
                                          float v0, float v1,
                                          const float* bias, const float* Res,
                                          int epi, int cvtout)
{
    v0 += bias[c];
    v1 += bias[c + 1];
    if (epi == 1) {
        v0 = 0.5f * v0 * (1.0f + erff(v0 * 0.70710678118654752f));
        v1 = 0.5f * v1 * (1.0f + erff(v1 * 0.70710678118654752f));
    } else if (epi == 2) {
        v0 += Res[off + c];
        v1 += Res[off + c + 1];
    }
    if (cvtout) {
        *(uint32_t*)((__half*)Cout + off + c) = f2h2(v0, v1);
    } else {
        *(float2*)((float*)Cout + off + c) = make_float2(v0, v1);
    }
}

// ---------------- FP16 tensor-core GEMM, 128x128 tile, ldmatrix consumer ----
// Round-13 proven structure: 256 threads = 8 warps of 32x64, BK=32 double-
// buffered, register prefetch -> MMA -> STS -> ONE barrier per slab.
// ROUND-14 CHANGE: smem layout [row][4 x 16B k-chunks], 80 B row stride
// (ldmatrix phase banks {0,4,...,28}: conflict-free); fragments loaded with
// ldmatrix.m8n8.x4 (12 per warp per slab vs 24 LDS.64).
constexpr int ROWB   = 80;               // bytes per smem row (64 data + 16 pad)
constexpr int STAGEB = 128 * ROWB;       // 10240 B per stage
// layout: A0 @0, A1 @STAGEB, B0 @2*STAGEB, B1 @3*STAGEB; total 40 KB

__global__ __launch_bounds__(256) void gemm_tc(const __half* __restrict__ A,
                                               const __half* __restrict__ W,
                                               const float* __restrict__ bias,
                                               const float* __restrict__ Res,
                                               void* __restrict__ Cout,
                                               int M, int K, int Nout, int epi, int cvtout)
{
    __shared__ __align__(16) char sm[4 * STAGEB];
    const uint32_t smb = (uint32_t)__cvta_generic_to_shared(sm);

    const int t = threadIdx.x;
    const int warp = t >> 5, lane = t & 31;
    const int g = lane >> 2, q = lane & 3;
    const int warpM = (warp >> 1) * 32;
    const int warpN = (warp & 1) * 64;

    // ---- producer mapping: thread t -> row t>>1, K16 half t&1 ----
    const int lrow = t >> 1;
    const int lks  = t & 1;
    int rowA = blockIdx.y * 128 + lrow;
    int rowW = blockIdx.x * 128 + lrow;
    if (rowA >= M) rowA = M - 1;          // clamp (stores are guarded)
    const __half* Ap = A + (size_t)rowA * K + lks * 16;
    const __half* Wp = W + (size_t)rowW * K + lks * 16;
    char* const psA = sm + lrow * ROWB + lks * 32;             // +0 / +16 chunks
    char* const psB = psA + 2 * STAGEB;

    // ---- consumer ldmatrix lane offsets (bytes within a stage) ----
    // A tile mt: rows warpM+mt*16+(L&15), chunk (L>>4); +ks*32 per ks.
    // B pair ntp: rows warpN+ntp*16+(L&7)+((L>>4)<<3), chunk ((L>>3)&1).
    const uint32_t offA0 = (uint32_t)((warpM + (lane & 15)) * ROWB + (lane >> 4) * 16);
    const uint32_t offB0 = (uint32_t)((warpN + (lane & 7) + ((lane >> 4) << 3)) * ROWB
                                      + ((lane >> 3) & 1) * 16);

    float acc[2][8][4];
    #pragma unroll
    for (int mt = 0; mt < 2; mt++)
        #pragma unroll
        for (int nt = 0; nt < 8; nt++)
            #pragma unroll
            for (int i = 0; i < 4; i++) acc[mt][nt][i] = 0.f;

    const int nk = K >> 5;

    // prologue: fill stage 0 (16 halves = 2 contiguous 16B chunks)
    {
        uint4 a0 = *(const uint4*)(Ap);
        uint4 a1 = *(const uint4*)(Ap + 8);
        uint4 w0 = *(const uint4*)(Wp);
        uint4 w1 = *(const uint4*)(Wp + 8);
        *(uint4*)(psA)      = a0;
        *(uint4*)(psA + 16) = a1;
        *(uint4*)(psB)      = w0;
        *(uint4*)(psB + 16) = w1;
    }
    __syncthreads();

    for (int kb = 0; kb < nk; kb++) {
        // prefetch next K-slab from global (registers held across compute)
        uint4 pa0, pa1, pw0, pw1;
        const bool more = (kb + 1) < nk;
        if (more) {
            const __half* An = Ap + (kb + 1) * 32;
            const __half* Wn = Wp + (kb + 1) * 32;
            pa0 = *(const uint4*)(An);
            pa1 = *(const uint4*)(An + 8);
            pw0 = *(const uint4*)(Wn);
            pw1 = *(const uint4*)(Wn + 8);
        }

        // compute current stage
        const uint32_t aBase = smb + (kb & 1) * STAGEB;
        const uint32_t bBase = aBase + 2 * STAGEB;
        #pragma unroll
        for (int ks = 0; ks < 2; ks++) {
            uint32_t af[2][4];
            uint32_t bf[8][2];
            #pragma unroll
            for (int mt = 0; mt < 2; mt++)
                ldm_x4(af[mt], aBase + offA0 + (uint32_t)(mt * 16 * ROWB + ks * 32));
            #pragma unroll
            for (int ntp = 0; ntp < 4; ntp++) {
                uint32_t bq[4];
                ldm_x4(bq, bBase + offB0 + (uint32_t)(ntp * 16 * ROWB + ks * 32));
                bf[2 * ntp][0]     = bq[0];
                bf[2 * ntp][1]     = bq[1];
                bf[2 * ntp + 1][0] = bq[2];
                bf[2 * ntp + 1][1] = bq[3];
            }
            #pragma unroll
            for (int mt = 0; mt < 2; mt++)
                #pragma unroll
                for (int nt = 0; nt < 8; nt++)
                    mma_f16(acc[mt][nt], af[mt], bf[nt]);
        }

        if (more) {
            char* dA = psA + ((kb + 1) & 1) * STAGEB - (kb & 1) * 0;  // stage offset below
            char* dst_a = sm + ((kb + 1) & 1) * STAGEB + lrow * ROWB + lks * 32;
            char* dst_b = dst_a + 2 * STAGEB;
            (void)dA;
            *(uint4*)(dst_a)      = pa0;
            *(uint4*)(dst_a + 16) = pa1;
            *(uint4*)(dst_b)      = pw0;
            *(uint4*)(dst_b + 16) = pw1;
        }
        __syncthreads();
    }

    // epilogue (fragment c layout identical to round 13)
    #pragma unroll
    for (int mt = 0; mt < 2; mt++) {
        #pragma unroll
        for (int half = 0; half < 2; half++) {
            const int r = blockIdx.y * 128 + warpM + mt * 16 + g + half * 8;
            if (r >= M) continue;
            const size_t off = (size_t)r * Nout;
            #pragma unroll
            for (int nt = 0; nt < 8; nt++) {
                const int c = blockIdx.x * 128 + warpN + nt * 8 + q * 2;
                epi_store(Cout, off, c, acc[mt][nt][half * 2 + 0], acc[mt][nt][half * 2 + 1],
                          bias, Res, epi, cvtout);
            }
        }
    }
}

// ---------------- fused block-diagonal attention (fp32 in, fp16 out) --------
constexpr int ATTN_SMEM = (SEQ * DH * 2 + 8 * SEQ + 8 * DH) * 4;

__global__ __launch_bounds__(256) void attn_kernel(const float* __restrict__ QKV,
                                                   __half* __restrict__ Out)
{
    extern __shared__ float smf[];
    float* Kt = smf;
    float* Vs = Kt + DH * SEQ;
    float* Sb = Vs + SEQ * DH;
    float* Qb = Sb + 8 * SEQ;

    int bh = blockIdx.x;
    int b = bh / HEADS, h = bh % HEADS;
    int base = b * SEQ;
    int qoff = h * DH, koff = E + h * DH, voff = 2 * E + h * DH;

    for (int idx = threadIdx.x; idx < SEQ * DH; idx += 256) {
        int j = idx >> 6, d = idx & 63;
        size_t rb = (size_t)(base + j) * E3;
        Kt[d * SEQ + j] = QKV[rb + koff + d];
        Vs[idx]         = QKV[rb + voff + d];
    }
    __syncthreads();

    int w = threadIdx.x >> 5, lane = threadIdx.x & 31;
    float* S = Sb + w * SEQ;
    float* Q = Qb + w * DH;

    for (int i = w; i < SEQ; i += 8) {
        const float* qp = QKV + (size_t)(base + i) * E3 + qoff;
        Q[lane]      = qp[lane];
        Q[lane + 32] = qp[lane + 32];
        __syncwarp();

        float sv[6];
        #pragma unroll
        for (int jj = 0; jj < 6; jj++) sv[jj] = 0.f;
        #pragma unroll 8
        for (int d = 0; d < DH; d++) {
            float qd = Q[d];
            const float* kr = Kt + d * SEQ;
            #pragma unroll
            for (int jj = 0; jj < 6; jj++)
                sv[jj] = fmaf(qd, kr[jj * 32 + lane], sv[jj]);
        }

        float mx = -3.0e38f;
        #pragma unroll
        for (int jj = 0; jj < 6; jj++) {
            int j = jj * 32 + lane;
            if (j < SEQ) { sv[jj] *= 0.125f; mx = fmaxf(mx, sv[jj]); }
        }
        #pragma unroll
        for (int o = 16; o; o >>= 1) mx = fmaxf(mx, __shfl_xor_sync(~0u, mx, o));

        float sum = 0.f;
        #pragma unroll
        for (int jj = 0; jj < 6; jj++) {
            int j = jj * 32 + lane;
            if (j < SEQ) { float e = __expf(sv[jj] - mx); S[j] = e; sum += e; }
        }
        #pragma unroll
        for (int o = 16; o; o >>= 1) sum += __shfl_xor_sync(~0u, sum, o);
        float inv = 1.0f / sum;
        __syncwarp();

        float o0 = 0.f, o1 = 0.f;
        for (int j = 0; j < SEQ; j++) {
            float p = S[j];
            o0 = fmaf(p, Vs[j * 64 + lane],      o0);
            o1 = fmaf(p, Vs[j * 64 + lane + 32], o1);
        }
        __half* op = Out + (size_t)(base + i) * E + qoff;
        op[lane]      = __float2half_rn(o0 * inv);
        op[lane + 32] = __float2half_rn(o1 * inv);
        __syncwarp();
    }
}

__global__ void fill_ones_kernel(float* p, int n)
{
    int i = blockIdx.x * blockDim.x + threadIdx.x;
    if (i < n) p[i] = 1.0f;
}

// ---------------- host orchestration ----------------
extern "C" void kernel_launch(void* const* d_in, const int* in_sizes, int n_in,
                              void* d_out, int out_size)
{
    const float* pixel   = (const float*)d_in[0];
    const float* patch_W = (const float*)d_in[1];
    const float* patch_b = (const float*)d_in[2];
    const float* row_emb = (const float*)d_in[3];
    const float* col_emb = (const float*)d_in[4];
    const float* cls     = (const float*)d_in[5];
    const float* ln1_g   = (const float*)d_in[6];
    const float* ln1_b   = (const float*)d_in[7];
    const float* in_w    = (const float*)d_in[8];
    const float* in_b    = (const float*)d_in[9];
    const float* out_w   = (const float*)d_in[10];
    const float* out_b   = (const float*)d_in[11];
    const float* ln2_g   = (const float*)d_in[12];
    const float* ln2_b   = (const float*)d_in[13];
    const float* mlp_w1  = (const float*)d_in[14];
    const float* mlp_b1  = (const float*)d_in[15];
    const float* mlp_w2  = (const float*)d_in[16];
    const float* mlp_b2  = (const float*)d_in[17];
    const float* fin_g   = (const float*)d_in[18];
    const float* fin_b   = (const float*)d_in[19];
    const float* br_w1   = (const float*)d_in[20];
    const float* br_b1   = (const float*)d_in[21];
    const float* br_w2   = (const float*)d_in[22];
    const float* br_b2   = (const float*)d_in[23];
    const float* br_g    = (const float*)d_in[24];
    const float* br_b    = (const float*)d_in[25];

    float *X, *QKV, *PE, *OUTP;
    __half *XN, *O, *H1, *PT;
    __half *Wpatch, *Win, *Wout, *Wm1, *Wm2, *Wb1, *Wb2;
    cudaGetSymbolAddress((void**)&X,    g_X);
    cudaGetSymbolAddress((void**)&XN,   g_XN);
    cudaGetSymbolAddress((void**)&QKV,  g_QKV);
    cudaGetSymbolAddress((void**)&O,    g_O);
    cudaGetSymbolAddress((void**)&H1,   g_H1);
    cudaGetSymbolAddress((void**)&PT,   g_PT);
    cudaGetSymbolAddress((void**)&PE,   g_PE);
    cudaGetSymbolAddress((void**)&OUTP, g_OUTP);
    cudaGetSymbolAddress((void**)&Wpatch, g_Wpatch);
    cudaGetSymbolAddress((void**)&Win,    g_Win);
    cudaGetSymbolAddress((void**)&Wout,   g_Wout);
    cudaGetSymbolAddress((void**)&Wm1,    g_Wm1);
    cudaGetSymbolAddress((void**)&Wm2,    g_Wm2);
    cudaGetSymbolAddress((void**)&Wb1,    g_Wb1);
    cudaGetSymbolAddress((void**)&Wb2,    g_Wb2);

    cudaFuncSetAttribute(attn_kernel, cudaFuncAttributeMaxDynamicSharedMemorySize, ATTN_SMEM);

    const int MPAT = Bn * NPAT;
    const dim3 blk(256);

    // ---- weight conversion (replayed each graph launch; ~100us) ----
    auto cvt = [&](const float* s, __half* d, int n) {
        cvt_kernel<<<(n / 8 + 255) / 256, blk>>>(s, d, n / 8);
    };
    cvt(patch_W, Wpatch, 768 * 768);
    cvt(in_w,    Win,    12 * 2304 * 768);
    cvt(out_w,   Wout,   12 * 768 * 768);
    cvt(mlp_w1,  Wm1,    12 * 3072 * 768);
    cvt(mlp_w2,  Wm2,    12 * 768 * 3072);
    cvt(br_w1,   Wb1,    1536 * 768);
    cvt(br_w2,   Wb2,    2048 * 1536);

    // ---- patch embedding ----
    patchify_kernel<<<(MPAT * E + 255) / 256, blk>>>(pixel, PT);
    gemm_tc<<<dim3(E / 128, MPAT / 128), blk>>>(PT, Wpatch, patch_b, nullptr, PE,
                                                MPAT, E, E, 0, 0);
    assemble_kernel<<<(Nrow * E + 255) / 256, blk>>>(PE, cls, row_emb, col_emb, X);

    const int GY = (Nrow + 127) / 128;   // 22

    for (int l = 0; l < Ll; l++) {
        ln_kernel<<<Nrow, blk>>>(X, ln1_g + l * E, ln1_b + l * E, XN, E, 1);
        gemm_tc<<<dim3(E3 / 128, GY), blk>>>(XN, Win + (size_t)l * E3 * E, in_b + (size_t)l * E3,
                                             nullptr, QKV, Nrow, E, E3, 0, 0);
        attn_kernel<<<Bn * HEADS, blk, ATTN_SMEM>>>(QKV, O);
        gemm_tc<<<dim3(E / 128, GY), blk>>>(O, Wout + (size_t)l * E * E, out_b + (size_t)l * E,
                                            X, X, Nrow, E, E, 2, 0);
        ln_kernel<<<Nrow, blk>>>(X, ln2_g + l * E, ln2_b + l * E, XN, E, 1);
        gemm_tc<<<dim3(MLPD / 128, GY), blk>>>(XN, Wm1 + (size_t)l * MLPD * E, mlp_b1 + (size_t)l * MLPD,
                                               nullptr, H1, Nrow, E, MLPD, 1, 1);
        gemm_tc<<<dim3(E / 128, GY), blk>>>(H1, Wm2 + (size_t)l * E * MLPD, mlp_b2 + (size_t)l * E,
                                            X, X, Nrow, MLPD, E, 2, 0);
    }

    ln_kernel<<<Nrow, blk>>>(X, fin_g, fin_b, XN, E, 1);
    gemm_tc<<<dim3(E2 / 128, GY), blk>>>(XN, Wb1, br_b1, nullptr, H1, Nrow, E, E2, 1, 1);
    gemm_tc<<<dim3(OUTD / 128, GY), blk>>>(H1, Wb2, br_b2, nullptr, OUTP, Nrow, E2, OUTD, 0, 0);
    ln_kernel<<<Nrow, blk>>>(OUTP, br_g, br_b, (float*)d_out, OUTD, 0);

    long long mainN = (long long)Nrow * OUTD;
    if ((long long)out_size > mainN) {
        int extra = (int)((long long)out_size - mainN);
        fill_ones_kernel<<<(extra + 255) / 256, blk>>>((float*)d_out + mainN, extra);
    }
}